// round 5
// baseline (speedup 1.0000x reference)
#include <cuda_runtime.h>
#include <cuda_bf16.h>
#include <math.h>

// Problem constants
#define NN 50000
#define NE 800000
#define DF 128
#define HID 64
#define CH 128

// ---------------- scratch (static __device__ globals; no allocations) -------
__device__ float g_P[NN * 128];      // per-node projections: [v][0:64]=Pr, [64:128]=Ps
__device__ float g_H[NN * 128];      // layer output features
__device__ float g_Bc[128 * 128];    // repacked W1 -> combined [128][128]
__device__ int   g_cnt[NN];
__device__ int   g_off[NN + 1];
__device__ int   g_cur[NN];
__device__ int   g_src[NE];          // senders sorted by receiver (CSR payload)

// packed f32x2 helpers (sm_100+ PTX; ptxas emits FFMA2)
#define FMA2(d, a, b) \
    asm("fma.rn.f32x2 %0, %1, %2, %0;" : "+l"(d) : "l"(a), "l"(b))
#define UNPACK2(lo, hi, p) \
    asm("mov.b64 {%0, %1}, %2;" : "=f"(lo), "=f"(hi) : "l"(p))

// ---------------- CSR construction -----------------------------------------
__global__ void zero_cnt_kernel() {
    int i = blockIdx.x * blockDim.x + threadIdx.x;
    if (i < NN) g_cnt[i] = 0;
}

__global__ void hist_kernel(const int* __restrict__ recv) {
    int i = blockIdx.x * blockDim.x + threadIdx.x;
    if (i < NE) atomicAdd(&g_cnt[recv[i]], 1);
}

// single-block 3-phase scan, register-light: phase 1 sums a contiguous
// 49-elem chunk per thread; phase 2 shuffle-scans the 1024 chunk sums;
// phase 3 RE-READS g_cnt (L2-hot) to emit prefixes. No per-thread arrays.
#define SCAN_C ((NN + 1023) / 1024)   // 49
__global__ void scan_kernel() {
    __shared__ int warp_tot[32];
    int tid = threadIdx.x;
    int base = tid * SCAN_C;
    int sum = 0;
    #pragma unroll 4
    for (int c = 0; c < SCAN_C; c++) {
        int idx = base + c;
        sum += (idx < NN) ? g_cnt[idx] : 0;
    }
    // warp-inclusive scan of chunk sums
    int lane = tid & 31, warp = tid >> 5;
    int incl = sum;
    #pragma unroll
    for (int o = 1; o < 32; o <<= 1) {
        int t = __shfl_up_sync(0xffffffffu, incl, o);
        if (lane >= o) incl += t;
    }
    if (lane == 31) warp_tot[warp] = incl;
    __syncthreads();
    if (warp == 0) {
        int w = warp_tot[lane];
        #pragma unroll
        for (int o = 1; o < 32; o <<= 1) {
            int t = __shfl_up_sync(0xffffffffu, w, o);
            if (lane >= o) w += t;
        }
        warp_tot[lane] = w;      // inclusive over warps
    }
    __syncthreads();
    int run = incl - sum + (warp > 0 ? warp_tot[warp - 1] : 0); // chunk-exclusive
    #pragma unroll 4
    for (int c = 0; c < SCAN_C; c++) {
        int idx = base + c;
        if (idx < NN) {
            g_off[idx] = run;
            g_cur[idx] = run;
            run += g_cnt[idx];
        }
    }
    if (tid == 1023) g_off[NN] = warp_tot[31];
}

__global__ void scatter_kernel(const int* __restrict__ recv,
                               const int* __restrict__ send) {
    int i = blockIdx.x * blockDim.x + threadIdx.x;
    if (i < NE) {
        int p = atomicAdd(&g_cur[recv[i]], 1);
        g_src[p] = send[i];
    }
}

// ---------------- repack W1 [256][64] -> Bc [128][128] ----------------------
// Bc[d][k] = W1[d][k] for k<64 (receiver half), W1[128+d][k-64] for k>=64 (sender half)
__global__ void repack_kernel(const float* __restrict__ W1) {
    int i = blockIdx.x * blockDim.x + threadIdx.x;
    if (i < 128 * 128) {
        int d = i >> 7, k = i & 127;
        g_Bc[i] = (k < 64) ? W1[d * 64 + k] : W1[(128 + d) * 64 + (k - 64)];
    }
}

// ---------------- node projection GEMM: C[M][128] = A[M][128] @ g_Bc --------
__global__ void gemm_nodeproj_kernel(const float* __restrict__ A,
                                     float* __restrict__ C, int M) {
    __shared__ __align__(16) float As[64][32];
    __shared__ __align__(16) float Bs[32][128];
    int tid = threadIdx.x;
    int rowBase = blockIdx.x * 64;
    int tr = (tid >> 5) * 8;       // 8 rows per thread
    int tc = (tid & 31) * 4;       // 4 cols per thread
    float acc[8][4];
    #pragma unroll
    for (int i = 0; i < 8; i++)
        #pragma unroll
        for (int j = 0; j < 4; j++) acc[i][j] = 0.f;

    for (int kt = 0; kt < 128; kt += 32) {
        #pragma unroll
        for (int i = 0; i < 8; i++) {           // 64*32 = 2048 elems
            int e = tid + i * 256;
            int r = e >> 5, c = e & 31;
            int gr = rowBase + r;
            As[r][c] = (gr < M) ? A[gr * 128 + kt + c] : 0.f;
        }
        #pragma unroll
        for (int i = 0; i < 16; i++) {          // 32*128 = 4096 elems
            int e = tid + i * 256;
            int r = e >> 7, c = e & 127;
            Bs[r][c] = g_Bc[(kt + r) * 128 + c];
        }
        __syncthreads();
        #pragma unroll
        for (int k = 0; k < 32; k++) {
            float4 b4 = *reinterpret_cast<const float4*>(&Bs[k][tc]);
            #pragma unroll
            for (int i = 0; i < 8; i++) {
                float a = As[tr + i][k];
                acc[i][0] += a * b4.x;
                acc[i][1] += a * b4.y;
                acc[i][2] += a * b4.z;
                acc[i][3] += a * b4.w;
            }
        }
        __syncthreads();
    }
    #pragma unroll
    for (int i = 0; i < 8; i++) {
        int gr = rowBase + tr + i;
        if (gr < M) {
            float4 o = make_float4(acc[i][0], acc[i][1], acc[i][2], acc[i][3]);
            *reinterpret_cast<float4*>(&C[gr * 128 + tc]) = o;
        }
    }
}

// ---------------- edge aggregation (the hot kernel) -------------------------
// One warp per node v. For each incoming edge (u -> v):
//   h[k]   = relu(Pr[v][k] + Ps[u][k] + b1[k]),      k in [0,64)
//   msg[j] = relu(sum_k h[k]*W2[k][j] + b2[j]),      j in [0,128)
//   acc   += msg ;  out[v] = acc / deg  (0 if deg==0)
//
// Packed-f32x2 k-split: lane l computes the pair {h[l], h[l+32]} per edge and
// stages it (one STS.64). W2 is pre-paired in smem: sW2p[k'][j] =
// {W2[k'][j], W2[k'+32][j]}. Each FFMA2 advances BOTH k-halves of the same
// output j; halves are folded (lo+hi) once per edge in the epilogue.
// Lanes own columns j = lane + 32m (m=0..3): conflict-free LDS.64 w reads.
// EB=8 main batch + EB=4 middle batch amortize W2 smem reads.
//
// DYNAMIC shared memory (54016 B > 48 KB static limit):
//   [0, 32768)      float2 sW2p[32*128]
//   [32768, 33280)  float  sb2[128]
//   [33280, 33536)  float  sb1[64]
//   [33536, 54016)  float2 hq[8 warps][32*HST]
#define AGG_WARPS 8
#define EB 8                       // edge batch
#define HST 10                     // hq row stride in float2 (16B-aligned rows, pad)
#define AGG_SMEM_BYTES (32768 + 512 + 256 + AGG_WARPS * 32 * HST * 8)

__global__ __launch_bounds__(256, 2)
void agg_kernel(const float* __restrict__ b1,
                const float* __restrict__ W2,
                const float* __restrict__ b2,
                float* __restrict__ out) {
    extern __shared__ __align__(16) char smem_raw[];
    float2* sW2p = reinterpret_cast<float2*>(smem_raw);
    float*  sb2  = reinterpret_cast<float*>(smem_raw + 32768);
    float*  sb1  = reinterpret_cast<float*>(smem_raw + 33280);
    float2* hq   = reinterpret_cast<float2*>(smem_raw + 33536);

    int tid = threadIdx.x;
    for (int i = tid; i < 32 * 128; i += blockDim.x) {
        int k = i >> 7, j = i & 127;
        sW2p[i] = make_float2(W2[k * 128 + j], W2[(k + 32) * 128 + j]);
    }
    if (tid < 128) sb2[tid] = b2[tid];
    if (tid < 64)  sb1[tid] = b1[tid];
    __syncthreads();

    int warp = tid >> 5, lane = tid & 31;
    float b2r[4];
    #pragma unroll
    for (int m = 0; m < 4; m++) b2r[m] = sb2[lane + 32 * m];
    float2* hwp = hq + warp * (32 * HST);

    for (int v = blockIdx.x * AGG_WARPS + warp; v < NN;
         v += gridDim.x * AGG_WARPS) {
        int beg = g_off[v], end = g_off[v + 1];
        float prb0 = g_P[v * 128 + lane]      + sb1[lane];
        float prb1 = g_P[v * 128 + 32 + lane] + sb1[lane + 32];
        float a[4] = {0.f, 0.f, 0.f, 0.f};

        int i = beg;
        // ---- EB=8 main batches ----
        for (; i + EB <= end; i += EB) {
            __syncwarp();
            #pragma unroll
            for (int t = 0; t < EB; t++) {
                int u = g_src[i + t];
                float h0 = fmaxf(prb0 + g_P[u * 128 + 64 + lane], 0.f);
                float h1 = fmaxf(prb1 + g_P[u * 128 + 96 + lane], 0.f);
                hwp[lane * HST + t] = make_float2(h0, h1);
            }
            __syncwarp();

            unsigned long long acc[4][EB];
            #pragma unroll
            for (int m = 0; m < 4; m++)
                #pragma unroll
                for (int t = 0; t < EB; t++) acc[m][t] = 0ull;

            #pragma unroll 8
            for (int kk = 0; kk < 32; kk++) {
                const ulonglong2* hrow =
                    reinterpret_cast<const ulonglong2*>(hwp + kk * HST);
                ulonglong2 hr0 = hrow[0], hr1 = hrow[1],
                           hr2 = hrow[2], hr3 = hrow[3];
                unsigned long long hp[EB] = {hr0.x, hr0.y, hr1.x, hr1.y,
                                             hr2.x, hr2.y, hr3.x, hr3.y};
                #pragma unroll
                for (int m = 0; m < 4; m++) {
                    unsigned long long w = *reinterpret_cast<const unsigned long long*>(
                        &sW2p[kk * 128 + lane + 32 * m]);
                    #pragma unroll
                    for (int t = 0; t < EB; t++) FMA2(acc[m][t], hp[t], w);
                }
            }
            #pragma unroll
            for (int t = 0; t < EB; t++) {
                #pragma unroll
                for (int m = 0; m < 4; m++) {
                    float lo, hi;
                    UNPACK2(lo, hi, acc[m][t]);
                    a[m] += fmaxf(lo + hi + b2r[m], 0.f);
                }
            }
        }
        // ---- EB=4 middle batch (at most one) ----
        if (i + 4 <= end) {
            __syncwarp();
            #pragma unroll
            for (int t = 0; t < 4; t++) {
                int u = g_src[i + t];
                float h0 = fmaxf(prb0 + g_P[u * 128 + 64 + lane], 0.f);
                float h1 = fmaxf(prb1 + g_P[u * 128 + 96 + lane], 0.f);
                hwp[lane * HST + t] = make_float2(h0, h1);
            }
            __syncwarp();
            unsigned long long acc[4][4];
            #pragma unroll
            for (int m = 0; m < 4; m++)
                #pragma unroll
                for (int t = 0; t < 4; t++) acc[m][t] = 0ull;
            #pragma unroll 8
            for (int kk = 0; kk < 32; kk++) {
                const ulonglong2* hrow =
                    reinterpret_cast<const ulonglong2*>(hwp + kk * HST);
                ulonglong2 hr0 = hrow[0], hr1 = hrow[1];
                unsigned long long hp[4] = {hr0.x, hr0.y, hr1.x, hr1.y};
                #pragma unroll
                for (int m = 0; m < 4; m++) {
                    unsigned long long w = *reinterpret_cast<const unsigned long long*>(
                        &sW2p[kk * 128 + lane + 32 * m]);
                    #pragma unroll
                    for (int t = 0; t < 4; t++) FMA2(acc[m][t], hp[t], w);
                }
            }
            #pragma unroll
            for (int t = 0; t < 4; t++) {
                #pragma unroll
                for (int m = 0; m < 4; m++) {
                    float lo, hi;
                    UNPACK2(lo, hi, acc[m][t]);
                    a[m] += fmaxf(lo + hi + b2r[m], 0.f);
                }
            }
            i += 4;
        }
        // ---- scalar tail (0..3 edges) ----
        for (; i < end; i++) {
            int u = g_src[i];
            float h0 = fmaxf(prb0 + g_P[u * 128 + 64 + lane], 0.f);
            float h1 = fmaxf(prb1 + g_P[u * 128 + 96 + lane], 0.f);
            __syncwarp();
            hwp[lane * HST] = make_float2(h0, h1);
            __syncwarp();
            unsigned long long acc[4] = {0ull, 0ull, 0ull, 0ull};
            #pragma unroll 8
            for (int kk = 0; kk < 32; kk++) {
                unsigned long long hp =
                    *reinterpret_cast<const unsigned long long*>(hwp + kk * HST);
                #pragma unroll
                for (int m = 0; m < 4; m++) {
                    unsigned long long w = *reinterpret_cast<const unsigned long long*>(
                        &sW2p[kk * 128 + lane + 32 * m]);
                    FMA2(acc[m], hp, w);
                }
            }
            #pragma unroll
            for (int m = 0; m < 4; m++) {
                float lo, hi;
                UNPACK2(lo, hi, acc[m]);
                a[m] += fmaxf(lo + hi + b2r[m], 0.f);
            }
        }
        int n = end - beg;
        float s = (n > 0) ? (1.f / (float)n) : 0.f;
        #pragma unroll
        for (int m = 0; m < 4; m++)
            out[v * 128 + lane + 32 * m] = a[m] * s;
    }
}

// ---------------- dense tail: out[v] = relu(H[v]@Wd1+bd1) @ Wd2 + bd2 -------
__global__ void dense_kernel(const float* __restrict__ Wd1,
                             const float* __restrict__ bd1,
                             const float* __restrict__ Wd2,
                             const float* __restrict__ bd2,
                             float* __restrict__ out) {
    __shared__ __align__(16) float sW[128 * 64];    // 32 KB
    __shared__ float sb1[64];
    __shared__ float sw2[64];
    __shared__ __align__(16) float shh[8][128];
    int tid = threadIdx.x;
    for (int i = tid; i < 128 * 64; i += blockDim.x) sW[i] = Wd1[i];
    if (tid < 64) { sb1[tid] = bd1[tid]; sw2[tid] = Wd2[tid]; }
    __syncthreads();
    float bias2 = bd2[0];
    int warp = tid >> 5, lane = tid & 31;
    for (int v = blockIdx.x * 8 + warp; v < NN; v += gridDim.x * 8) {
        float4 hv = *reinterpret_cast<const float4*>(&g_H[v * 128 + lane * 4]);
        __syncwarp();
        *reinterpret_cast<float4*>(&shh[warp][lane * 4]) = hv;
        __syncwarp();
        float a0 = 0.f, a1 = 0.f;
        #pragma unroll
        for (int d = 0; d < 128; d++) {
            float hd = shh[warp][d];
            a0 += hd * sW[d * 64 + lane];
            a1 += hd * sW[d * 64 + lane + 32];
        }
        float t0 = fmaxf(a0 + sb1[lane], 0.f);
        float t1 = fmaxf(a1 + sb1[lane + 32], 0.f);
        float p = t0 * sw2[lane] + t1 * sw2[lane + 32];
        #pragma unroll
        for (int o = 16; o > 0; o >>= 1)
            p += __shfl_xor_sync(0xffffffffu, p, o);
        if (lane == 0) out[v] = p + bias2;
    }
}

// ---------------- launch ----------------------------------------------------
extern "C" void kernel_launch(void* const* d_in, const int* in_sizes, int n_in,
                              void* d_out, int out_size) {
    const float* x    = (const float*)d_in[0];
    const int*   send = (const int*)d_in[1];
    const int*   recv = (const int*)d_in[2];
    const float* W1a  = (const float*)d_in[3];
    const float* b1a  = (const float*)d_in[4];
    const float* W2a  = (const float*)d_in[5];
    const float* b2a  = (const float*)d_in[6];
    const float* W1b  = (const float*)d_in[7];
    const float* b1b  = (const float*)d_in[8];
    const float* W2b  = (const float*)d_in[9];
    const float* b2b  = (const float*)d_in[10];
    const float* Wd1  = (const float*)d_in[11];
    const float* bd1  = (const float*)d_in[12];
    const float* Wd2  = (const float*)d_in[13];
    const float* bd2  = (const float*)d_in[14];
    float* out = (float*)d_out;

    float* pP; cudaGetSymbolAddress((void**)&pP, g_P);
    float* pH; cudaGetSymbolAddress((void**)&pH, g_H);

    // agg_kernel needs >48KB dynamic smem; attribute set is idempotent and
    // not stream-ordered (graph-capture safe).
    cudaFuncSetAttribute(agg_kernel,
                         cudaFuncAttributeMaxDynamicSharedMemorySize,
                         AGG_SMEM_BYTES);

    // CSR by receiver
    zero_cnt_kernel<<<(NN + 255) / 256, 256>>>();
    hist_kernel<<<(NE + 255) / 256, 256>>>(recv);
    scan_kernel<<<1, 1024>>>();
    scatter_kernel<<<(NE + 255) / 256, 256>>>(recv, send);

    int gemm_blocks = (NN + 63) / 64;
    int agg_blocks  = (NN + AGG_WARPS - 1) / AGG_WARPS;

    // Layer a: P = x @ [W1a_recv | W1a_send]; aggregate -> H
    repack_kernel<<<64, 256>>>(W1a);
    gemm_nodeproj_kernel<<<gemm_blocks, 256>>>(x, pP, NN);
    agg_kernel<<<agg_blocks, 256, AGG_SMEM_BYTES>>>(b1a, W2a, b2a, pH);

    // Layer b: P = H @ [W1b_recv | W1b_send]; aggregate -> H (reads only P/CSR)
    repack_kernel<<<64, 256>>>(W1b);
    gemm_nodeproj_kernel<<<gemm_blocks, 256>>>(pH, pP, NN);
    agg_kernel<<<agg_blocks, 256, AGG_SMEM_BYTES>>>(b1b, W2b, b2b, pH);

    // Dense tail -> output [NN, 1]
    dense_kernel<<<agg_blocks, 256>>>(Wd1, bd1, Wd2, bd2, out);
}